// round 2
// baseline (speedup 1.0000x reference)
#include <cuda_runtime.h>

#define NNODES 50000
#define NEDGES 200000
#define NGRAPH 2048
#define D_IN   64
#define D_H    1000
#define D_ENC  128

// ---------------- scratch (static device allocations; no cudaMalloc) --------
__device__ float g_aggx[NNODES * D_IN];              // 12.8 MB
__device__ float g_h1[(size_t)NNODES * D_H];         // 200 MB
__device__ float g_z2[NNODES * 256];                 // 51.2 MB  (cols 0..127 = rel, 128..255 = root)
__device__ float g_aggy[NNODES * D_ENC];             // 25.6 MB
__device__ float g_h2[NNODES * D_ENC];               // 25.6 MB
__device__ float g_aggh2[NNODES * D_ENC];            // 25.6 MB
__device__ float g_h3[(size_t)NNODES * D_H];         // 200 MB
__device__ float g_z4[NNODES * 128];                 // 25.6 MB  (cols 0..63 = rel, 64..127 = root)
__device__ float g_sums[NGRAPH * D_ENC];
__device__ float g_counts[NGRAPH];
__device__ int   g_ei32[2 * NEDGES];
__device__ int   g_batch32[NNODES];
__device__ int   g_is64;

// ---------------- dtype detection + conversion ------------------------------
// JAX without x64 silently downcasts int64->int32. Detect which we got:
// little-endian int64 values < 50000 have every odd int32 word == 0.
__global__ void detect_kernel(const int* __restrict__ ei_raw) {
    int odd_zero = 1;
    #pragma unroll
    for (int i = 0; i < 16; ++i)
        if (ei_raw[2 * i + 1] != 0) odd_zero = 0;
    g_is64 = odd_zero;
}

__global__ void convert_kernel(const int* __restrict__ ei_raw,
                               const int* __restrict__ batch_raw) {
    int i = blockIdx.x * blockDim.x + threadIdx.x;
    int is64 = g_is64;
    if (i < 2 * NEDGES) g_ei32[i] = is64 ? ei_raw[2 * i] : ei_raw[i];
    if (i < NNODES)     g_batch32[i] = is64 ? batch_raw[2 * i] : batch_raw[i];
}

// ---------------- utility kernels -------------------------------------------
__global__ void zero_kernel(float* p, int n) {
    for (int i = blockIdx.x * blockDim.x + threadIdx.x; i < n; i += gridDim.x * blockDim.x)
        p[i] = 0.f;
}

// segment-sum over edges: out[dst, f] += feat[src, f], f in [0, F)
template <int F>
__global__ void edge_agg_kernel(const float* __restrict__ feat, int featStride,
                                float* __restrict__ out, int outStride) {
    int idx = blockIdx.x * blockDim.x + threadIdx.x;
    int e = idx / F;
    int f = idx & (F - 1);
    if (e < NEDGES) {
        int s = g_ei32[e];
        int d = g_ei32[NEDGES + e];
        atomicAdd(&out[(size_t)d * outStride + f], feat[(size_t)s * featStride + f]);
    }
}

// h2 = relu(aggy + z2[:,128:256] + b2)
__global__ void combine_h2_kernel(const float* __restrict__ b2) {
    int idx = blockIdx.x * blockDim.x + threadIdx.x;
    if (idx >= NNODES * D_ENC) return;
    int i = idx >> 7, f = idx & 127;
    float v = g_aggy[idx] + g_z2[(size_t)i * 256 + 128 + f] + b2[f];
    g_h2[idx] = fmaxf(v, 0.f);
}

__global__ void pool_kernel() {
    int idx = blockIdx.x * blockDim.x + threadIdx.x;
    if (idx >= NNODES * D_ENC) return;
    int i = idx >> 7, f = idx & 127;
    int b = g_batch32[i];
    atomicAdd(&g_sums[b * D_ENC + f], g_h2[idx]);
    if (f == 0) atomicAdd(&g_counts[b], 1.f);
}

__global__ void encoded_kernel(float* __restrict__ enc) {
    int idx = blockIdx.x * blockDim.x + threadIdx.x;
    if (idx >= NGRAPH * D_ENC) return;
    int g = idx >> 7;
    enc[idx] = g_sums[idx] / fmaxf(g_counts[g], 1.f);
}

// out[i,f] = z4[i,64+f] + b4[f]  (root term + bias; edge term atomically added after)
__global__ void out_init_kernel(float* __restrict__ out, const float* __restrict__ b4) {
    int idx = blockIdx.x * blockDim.x + threadIdx.x;
    if (idx >= NNODES * D_IN) return;
    int i = idx >> 6, f = idx & 63;
    out[idx] = g_z4[(size_t)i * 128 + 64 + f] + b4[f];
}

// ---------------- SGEMM: C[N,O] = act( sum-of-products + bias ) -------------
// DUAL_A: C = A1 @ W1^T + A2 @ W2^T                (shared cols; W [O,K])
// DUAL_W: C[:, o] = A1 @ (o<Osplit ? W1 row o : W2 row o-Osplit)^T
#define BM 64
#define BN 64
#define BK 16

template <bool DUAL_A, bool RELU, bool BIAS>
__global__ void __launch_bounds__(256) gemm_kernel(
    float* __restrict__ C,
    const float* __restrict__ A1, const float* __restrict__ A2,
    const float* __restrict__ W1, const float* __restrict__ W2,
    const float* __restrict__ bias,
    int Nn, int K, int O, int Osplit) {

    __shared__ float As[BK][BM];
    __shared__ float Ws[BK][BN + 4];

    int tid = threadIdx.x;
    int tx = tid & 15, ty = tid >> 4;
    int rowBase = blockIdx.y * BM;
    int colBase = blockIdx.x * BN;

    float acc[4][4] = {};

    // weight selection for the DUAL_W (single-A) case: one side per 64-col block
    const float* WblkSingle = W1;
    int wrbSingle = colBase;
    if (!DUAL_A) {
        if (colBase >= Osplit) { WblkSingle = W2; wrbSingle = colBase - Osplit; }
    }

    const int nPasses = DUAL_A ? 2 : 1;
    for (int pass = 0; pass < nPasses; ++pass) {
        const float* A = (pass == 0) ? A1 : A2;
        const float* W = DUAL_A ? ((pass == 0) ? W1 : W2) : WblkSingle;
        int wrb        = DUAL_A ? colBase : wrbSingle;

        for (int kb = 0; kb < K; kb += BK) {
            // load A tile: As[k][m] = A[(rowBase+m)*K + kb+k]
            int lm = tid >> 2;
            int lk = (tid & 3) * 4;
            int row = rowBase + lm;
            #pragma unroll
            for (int u = 0; u < 4; ++u) {
                int k = lk + u;
                float v = 0.f;
                if (row < Nn && kb + k < K) v = A[(size_t)row * K + kb + k];
                As[k][lm] = v;
            }
            // load W tile: Ws[k][n] = W[(wrb+n)*K + kb+k]
            int ln = lm;
            #pragma unroll
            for (int u = 0; u < 4; ++u) {
                int k = lk + u;
                float v = 0.f;
                if (colBase + ln < O && kb + k < K) v = W[(size_t)(wrb + ln) * K + kb + k];
                Ws[k][ln] = v;
            }
            __syncthreads();

            #pragma unroll
            for (int k = 0; k < BK; ++k) {
                float4 av = reinterpret_cast<const float4*>(&As[k][0])[ty];
                float4 bv = reinterpret_cast<const float4*>(&Ws[k][0])[tx];
                float a[4] = {av.x, av.y, av.z, av.w};
                float b[4] = {bv.x, bv.y, bv.z, bv.w};
                #pragma unroll
                for (int i = 0; i < 4; ++i)
                    #pragma unroll
                    for (int j = 0; j < 4; ++j)
                        acc[i][j] += a[i] * b[j];
            }
            __syncthreads();
        }
    }

    // epilogue (O is always a multiple of 4; col is a multiple of 4)
    #pragma unroll
    for (int i = 0; i < 4; ++i) {
        int row = rowBase + ty * 4 + i;
        if (row >= Nn) continue;
        int col = colBase + tx * 4;
        if (col >= O) continue;
        float4 v;
        float* vv = reinterpret_cast<float*>(&v);
        #pragma unroll
        for (int j = 0; j < 4; ++j) {
            float x = acc[i][j];
            if (BIAS) x += bias[col + j];
            if (RELU) x = fmaxf(x, 0.f);
            vv[j] = x;
        }
        reinterpret_cast<float4*>(&C[(size_t)row * O + col])[0] = v;
    }
}

// ---------------- launch ----------------------------------------------------
extern "C" void kernel_launch(void* const* d_in, const int* in_sizes, int n_in,
                              void* d_out, int out_size) {
    const float* x        = (const float*)d_in[0];
    const int*   ei_raw   = (const int*)d_in[1];    // int32 OR int64 (detected on device)
    const int*   batch_raw= (const int*)d_in[2];
    const float* W1_rel   = (const float*)d_in[3];
    const float* b1       = (const float*)d_in[4];
    const float* W1_root  = (const float*)d_in[5];
    const float* W2_rel   = (const float*)d_in[6];
    const float* b2       = (const float*)d_in[7];
    const float* W2_root  = (const float*)d_in[8];
    const float* W3_rel   = (const float*)d_in[9];
    const float* b3       = (const float*)d_in[10];
    const float* W3_root  = (const float*)d_in[11];
    const float* W4_rel   = (const float*)d_in[12];
    const float* b4       = (const float*)d_in[13];
    const float* W4_root  = (const float*)d_in[14];

    float* out = (float*)d_out;              // [N,64] then encoded [G,128]
    float* enc = out + (size_t)NNODES * D_IN;

    float *aggx, *h1, *z2, *aggy, *h2, *aggh2, *h3, *z4, *sums, *counts;
    cudaGetSymbolAddress((void**)&aggx,   g_aggx);
    cudaGetSymbolAddress((void**)&h1,     g_h1);
    cudaGetSymbolAddress((void**)&z2,     g_z2);
    cudaGetSymbolAddress((void**)&aggy,   g_aggy);
    cudaGetSymbolAddress((void**)&h2,     g_h2);
    cudaGetSymbolAddress((void**)&aggh2,  g_aggh2);
    cudaGetSymbolAddress((void**)&h3,     g_h3);
    cudaGetSymbolAddress((void**)&z4,     g_z4);
    cudaGetSymbolAddress((void**)&sums,   g_sums);
    cudaGetSymbolAddress((void**)&counts, g_counts);

    const int T = 256;
    const int rowBlocks = (NNODES + BM - 1) / BM;   // 782

    // ---- dtype detect + index conversion
    detect_kernel<<<1, 1>>>(ei_raw);
    convert_kernel<<<(2 * NEDGES + T - 1) / T, T>>>(ei_raw, batch_raw);

    // ---- L1: aggregate x (64-dim) then dual-A GEMM -> h1 = relu(...)
    zero_kernel<<<1024, T>>>(aggx, NNODES * D_IN);
    edge_agg_kernel<64><<<(NEDGES * 64 + T - 1) / T, T>>>(x, D_IN, aggx, D_IN);
    {
        dim3 grid((D_H + BN - 1) / BN, rowBlocks);
        gemm_kernel<true, true, true><<<grid, T>>>(h1, aggx, x, W1_rel, W1_root, b1,
                                                   NNODES, D_IN, D_H, 0);
    }

    // ---- L2: dual-W GEMM (K=1000) -> z2 [N,256]; aggregate cols 0..127; combine
    {
        dim3 grid(256 / BN, rowBlocks);
        gemm_kernel<false, false, false><<<grid, T>>>(z2, h1, nullptr, W2_rel, W2_root,
                                                      nullptr, NNODES, D_H, 256, 128);
    }
    zero_kernel<<<1024, T>>>(aggy, NNODES * D_ENC);
    edge_agg_kernel<128><<<(NEDGES * 128 + T - 1) / T, T>>>(z2, 256, aggy, D_ENC);
    combine_h2_kernel<<<(NNODES * D_ENC + T - 1) / T, T>>>(b2);

    // ---- pooling -> encoded
    zero_kernel<<<256, T>>>(sums, NGRAPH * D_ENC);
    zero_kernel<<<8, T>>>(counts, NGRAPH);
    pool_kernel<<<(NNODES * D_ENC + T - 1) / T, T>>>();
    encoded_kernel<<<(NGRAPH * D_ENC + T - 1) / T, T>>>(enc);

    // ---- L3: aggregate h2 (128-dim) then dual-A GEMM -> h3 = relu(...)
    zero_kernel<<<1024, T>>>(aggh2, NNODES * D_ENC);
    edge_agg_kernel<128><<<(NEDGES * 128 + T - 1) / T, T>>>(h2, D_ENC, aggh2, D_ENC);
    {
        dim3 grid((D_H + BN - 1) / BN, rowBlocks);
        gemm_kernel<true, true, true><<<grid, T>>>(h3, aggh2, h2, W3_rel, W3_root, b3,
                                                   NNODES, D_ENC, D_H, 0);
    }

    // ---- L4: dual-W GEMM (K=1000) -> z4 [N,128]; out = seg_sum(z4[:, :64]) + z4[:,64:] + b4
    {
        dim3 grid(128 / BN, rowBlocks);
        gemm_kernel<false, false, false><<<grid, T>>>(z4, h3, nullptr, W4_rel, W4_root,
                                                      nullptr, NNODES, D_H, 128, 64);
    }
    out_init_kernel<<<(NNODES * D_IN + T - 1) / T, T>>>(out, b4);
    edge_agg_kernel<64><<<(NEDGES * 64 + T - 1) / T, T>>>(z4, 128, out, D_IN);
}

// round 3
// speedup vs baseline: 1.5662x; 1.5662x over previous
#include <cuda_runtime.h>

#define NNODES 50000
#define NEDGES 200000
#define NGRAPH 2048
#define D_IN   64
#define D_H    1000
#define D_ENC  128

// ---------------- scratch (static device allocations; no cudaMalloc) --------
__device__ float g_aggx[NNODES * D_IN];
__device__ float g_h1[(size_t)NNODES * D_H];
__device__ float g_z2[NNODES * 256];     // cols 0..127 = rel, 128..255 = root
__device__ float g_aggy[NNODES * D_ENC];
__device__ float g_h2[NNODES * D_ENC];
__device__ float g_aggh2[NNODES * D_ENC];
__device__ float g_h3[(size_t)NNODES * D_H];
__device__ float g_z4[NNODES * 128];     // cols 0..63 = rel, 64..127 = root
__device__ float g_sums[NGRAPH * D_ENC];
__device__ float g_counts[NGRAPH];
__device__ int   g_ei32[2 * NEDGES];
__device__ int   g_batch32[NNODES];
__device__ int   g_is64;

// ---------------- dtype detection + conversion ------------------------------
__global__ void detect_kernel(const int* __restrict__ ei_raw) {
    int odd_zero = 1;
    #pragma unroll
    for (int i = 0; i < 16; ++i)
        if (ei_raw[2 * i + 1] != 0) odd_zero = 0;
    g_is64 = odd_zero;
}

__global__ void convert_kernel(const int* __restrict__ ei_raw,
                               const int* __restrict__ batch_raw) {
    int i = blockIdx.x * blockDim.x + threadIdx.x;
    int is64 = g_is64;
    if (i < 2 * NEDGES) g_ei32[i] = is64 ? ei_raw[2 * i] : ei_raw[i];
    if (i < NNODES)     g_batch32[i] = is64 ? batch_raw[2 * i] : batch_raw[i];
}

// ---------------- utility kernels -------------------------------------------
__global__ void zero_kernel(float* p, int n) {
    for (int i = blockIdx.x * blockDim.x + threadIdx.x; i < n; i += gridDim.x * blockDim.x)
        p[i] = 0.f;
}

// segment-sum over edges, vectorized: each thread does 4 features of one edge
template <int F>
__global__ void edge_agg_kernel(const float* __restrict__ feat, int featStride,
                                float* __restrict__ out, int outStride) {
    constexpr int V = F / 4;
    int idx = blockIdx.x * blockDim.x + threadIdx.x;
    int e = idx / V;
    int f = (idx % V) * 4;
    if (e >= NEDGES) return;
    int s = g_ei32[e];
    int d = g_ei32[NEDGES + e];
    float4 v = *reinterpret_cast<const float4*>(&feat[(size_t)s * featStride + f]);
    float* o = &out[(size_t)d * outStride + f];
    atomicAdd(o + 0, v.x);
    atomicAdd(o + 1, v.y);
    atomicAdd(o + 2, v.z);
    atomicAdd(o + 3, v.w);
}

// h2 = relu(aggy + z2[:,128:256] + b2)
__global__ void combine_h2_kernel(const float* __restrict__ b2) {
    int idx = blockIdx.x * blockDim.x + threadIdx.x;
    if (idx >= NNODES * D_ENC) return;
    int i = idx >> 7, f = idx & 127;
    float v = g_aggy[idx] + g_z2[(size_t)i * 256 + 128 + f] + b2[f];
    g_h2[idx] = fmaxf(v, 0.f);
}

__global__ void pool_kernel() {
    int idx = blockIdx.x * blockDim.x + threadIdx.x;
    if (idx >= NNODES * D_ENC) return;
    int i = idx >> 7, f = idx & 127;
    int b = g_batch32[i];
    atomicAdd(&g_sums[b * D_ENC + f], g_h2[idx]);
    if (f == 0) atomicAdd(&g_counts[b], 1.f);
}

__global__ void encoded_kernel(float* __restrict__ enc) {
    int idx = blockIdx.x * blockDim.x + threadIdx.x;
    if (idx >= NGRAPH * D_ENC) return;
    int g = idx >> 7;
    enc[idx] = g_sums[idx] / fmaxf(g_counts[g], 1.f);
}

__global__ void out_init_kernel(float* __restrict__ out, const float* __restrict__ b4) {
    int idx = blockIdx.x * blockDim.x + threadIdx.x;
    if (idx >= NNODES * D_IN) return;
    int i = idx >> 6, f = idx & 63;
    out[idx] = g_z4[(size_t)i * 128 + 64 + f] + b4[f];
}

// ---------------- SGEMM 128x128xK, BK=8, 256 thr, 8x8/thread ----------------
// DUAL_A: C = A1 @ W1^T + A2 @ W2^T        (W [O,K] row-major)
// DUAL_W: C[:, o] = A1 @ (o<Osplit ? W1[o] : W2[o-Osplit])^T
#define BM 128
#define BN 128
#define BK 8
#define LDP 132   // smem row pad (16B-aligned, conflict-free)

template <bool DUAL_A, bool RELU, bool BIAS>
__global__ void __launch_bounds__(256, 2) gemm128(
    float* __restrict__ C,
    const float* __restrict__ A1, const float* __restrict__ A2,
    const float* __restrict__ W1, const float* __restrict__ W2,
    const float* __restrict__ bias,
    int Nn, int K, int O, int Osplit) {

    __shared__ float As[2][BK][LDP];
    __shared__ float Ws[2][BK][LDP];

    const int tid = threadIdx.x;
    const int tx = tid & 15, ty = tid >> 4;
    const int rowBase = blockIdx.y * BM;
    const int colBase = blockIdx.x * BN;

    // loader mapping: lm = row/col within tile, lk = k offset (0 or 4)
    const int lm = tid >> 1;
    const int lk = (tid & 1) * 4;

    const int arow = rowBase + lm;
    const bool arow_ok = (arow < Nn);
    const int wcol = colBase + lm;

    // per-thread weight row pointers
    const float* wrow0 = nullptr;
    const float* wrow1 = nullptr;
    if (DUAL_A) {
        if (wcol < O) { wrow0 = W1 + (size_t)wcol * K; wrow1 = W2 + (size_t)wcol * K; }
    } else {
        if (wcol < O) {
            wrow0 = (wcol < Osplit) ? (W1 + (size_t)wcol * K)
                                    : (W2 + (size_t)(wcol - Osplit) * K);
        }
    }

    const int nk = K / BK;                  // K is always a multiple of 8
    const int total = DUAL_A ? 2 * nk : nk;

    float acc[2][2][4][4] = {};
    float4 pa, pw;

    auto prefetch = [&](int t) {
        const float* A = A1;
        const float* Wr = wrow0;
        int tt = t;
        if (DUAL_A && t >= nk) { A = A2; Wr = wrow1; tt = t - nk; }
        int kb = tt * BK + lk;
        pa = make_float4(0.f, 0.f, 0.f, 0.f);
        pw = make_float4(0.f, 0.f, 0.f, 0.f);
        if (arow_ok) pa = *reinterpret_cast<const float4*>(&A[(size_t)arow * K + kb]);
        if (Wr)      pw = *reinterpret_cast<const float4*>(&Wr[kb]);
    };
    auto stash = [&](int b) {
        As[b][lk + 0][lm] = pa.x; As[b][lk + 1][lm] = pa.y;
        As[b][lk + 2][lm] = pa.z; As[b][lk + 3][lm] = pa.w;
        Ws[b][lk + 0][lm] = pw.x; Ws[b][lk + 1][lm] = pw.y;
        Ws[b][lk + 2][lm] = pw.z; Ws[b][lk + 3][lm] = pw.w;
    };

    prefetch(0);
    stash(0);
    __syncthreads();

    int buf = 0;
    for (int t = 0; t < total; ++t) {
        if (t + 1 < total) prefetch(t + 1);

        #pragma unroll
        for (int k = 0; k < BK; ++k) {
            float4 a0 = *reinterpret_cast<const float4*>(&As[buf][k][ty * 4]);
            float4 a1 = *reinterpret_cast<const float4*>(&As[buf][k][ty * 4 + 64]);
            float4 b0 = *reinterpret_cast<const float4*>(&Ws[buf][k][tx * 4]);
            float4 b1 = *reinterpret_cast<const float4*>(&Ws[buf][k][tx * 4 + 64]);
            float av[2][4] = {{a0.x, a0.y, a0.z, a0.w}, {a1.x, a1.y, a1.z, a1.w}};
            float bv[2][4] = {{b0.x, b0.y, b0.z, b0.w}, {b1.x, b1.y, b1.z, b1.w}};
            #pragma unroll
            for (int ri = 0; ri < 2; ++ri)
                #pragma unroll
                for (int ci = 0; ci < 2; ++ci)
                    #pragma unroll
                    for (int i = 0; i < 4; ++i)
                        #pragma unroll
                        for (int j = 0; j < 4; ++j)
                            acc[ri][ci][i][j] += av[ri][i] * bv[ci][j];
        }

        if (t + 1 < total) {
            stash(buf ^ 1);
            __syncthreads();
            buf ^= 1;
        }
    }

    // epilogue: O and cols are multiples of 4 -> float4 stores with col<O guard
    #pragma unroll
    for (int ri = 0; ri < 2; ++ri) {
        #pragma unroll
        for (int i = 0; i < 4; ++i) {
            int row = rowBase + ri * 64 + ty * 4 + i;
            if (row >= Nn) continue;
            #pragma unroll
            for (int ci = 0; ci < 2; ++ci) {
                int col = colBase + ci * 64 + tx * 4;
                if (col >= O) continue;
                float4 v;
                float* vv = reinterpret_cast<float*>(&v);
                #pragma unroll
                for (int j = 0; j < 4; ++j) {
                    float xq = acc[ri][ci][i][j];
                    if (BIAS) xq += bias[col + j];
                    if (RELU) xq = fmaxf(xq, 0.f);
                    vv[j] = xq;
                }
                *reinterpret_cast<float4*>(&C[(size_t)row * O + col]) = v;
            }
        }
    }
}

// ---------------- launch ----------------------------------------------------
extern "C" void kernel_launch(void* const* d_in, const int* in_sizes, int n_in,
                              void* d_out, int out_size) {
    const float* x        = (const float*)d_in[0];
    const int*   ei_raw   = (const int*)d_in[1];
    const int*   batch_raw= (const int*)d_in[2];
    const float* W1_rel   = (const float*)d_in[3];
    const float* b1       = (const float*)d_in[4];
    const float* W1_root  = (const float*)d_in[5];
    const float* W2_rel   = (const float*)d_in[6];
    const float* b2       = (const float*)d_in[7];
    const float* W2_root  = (const float*)d_in[8];
    const float* W3_rel   = (const float*)d_in[9];
    const float* b3       = (const float*)d_in[10];
    const float* W3_root  = (const float*)d_in[11];
    const float* W4_rel   = (const float*)d_in[12];
    const float* b4       = (const float*)d_in[13];
    const float* W4_root  = (const float*)d_in[14];

    float* out = (float*)d_out;              // [N,64] then encoded [G,128]
    float* enc = out + (size_t)NNODES * D_IN;

    float *aggx, *h1, *z2, *aggy, *h2, *aggh2, *h3, *z4, *sums, *counts;
    cudaGetSymbolAddress((void**)&aggx,   g_aggx);
    cudaGetSymbolAddress((void**)&h1,     g_h1);
    cudaGetSymbolAddress((void**)&z2,     g_z2);
    cudaGetSymbolAddress((void**)&aggy,   g_aggy);
    cudaGetSymbolAddress((void**)&h2,     g_h2);
    cudaGetSymbolAddress((void**)&aggh2,  g_aggh2);
    cudaGetSymbolAddress((void**)&h3,     g_h3);
    cudaGetSymbolAddress((void**)&z4,     g_z4);
    cudaGetSymbolAddress((void**)&sums,   g_sums);
    cudaGetSymbolAddress((void**)&counts, g_counts);

    const int T = 256;
    const int rowBlocks = (NNODES + BM - 1) / BM;   // 391

    // ---- dtype detect + index conversion
    detect_kernel<<<1, 1>>>(ei_raw);
    convert_kernel<<<(2 * NEDGES + T - 1) / T, T>>>(ei_raw, batch_raw);

    // ---- L1: aggregate x (64-dim) then dual-A GEMM -> h1 = relu(...)
    zero_kernel<<<1024, T>>>(aggx, NNODES * D_IN);
    edge_agg_kernel<64><<<(NEDGES * 16 + T - 1) / T, T>>>(x, D_IN, aggx, D_IN);
    {
        dim3 grid((D_H + BN - 1) / BN, rowBlocks);
        gemm128<true, true, true><<<grid, T>>>(h1, aggx, x, W1_rel, W1_root, b1,
                                               NNODES, D_IN, D_H, 0);
    }

    // ---- L2: dual-W GEMM (K=1000) -> z2 [N,256]; aggregate cols 0..127; combine
    {
        dim3 grid(256 / BN, rowBlocks);
        gemm128<false, false, false><<<grid, T>>>(z2, h1, nullptr, W2_rel, W2_root,
                                                  nullptr, NNODES, D_H, 256, 128);
    }
    zero_kernel<<<1024, T>>>(aggy, NNODES * D_ENC);
    edge_agg_kernel<128><<<(NEDGES * 32 + T - 1) / T, T>>>(z2, 256, aggy, D_ENC);
    combine_h2_kernel<<<(NNODES * D_ENC + T - 1) / T, T>>>(b2);

    // ---- pooling -> encoded
    zero_kernel<<<256, T>>>(sums, NGRAPH * D_ENC);
    zero_kernel<<<8, T>>>(counts, NGRAPH);
    pool_kernel<<<(NNODES * D_ENC + T - 1) / T, T>>>();
    encoded_kernel<<<(NGRAPH * D_ENC + T - 1) / T, T>>>(enc);

    // ---- L3: aggregate h2 (128-dim) then dual-A GEMM -> h3 = relu(...)
    zero_kernel<<<1024, T>>>(aggh2, NNODES * D_ENC);
    edge_agg_kernel<128><<<(NEDGES * 32 + T - 1) / T, T>>>(h2, D_ENC, aggh2, D_ENC);
    {
        dim3 grid((D_H + BN - 1) / BN, rowBlocks);
        gemm128<true, true, true><<<grid, T>>>(h3, aggh2, h2, W3_rel, W3_root, b3,
                                               NNODES, D_ENC, D_H, 0);
    }

    // ---- L4: dual-W GEMM (K=1000) -> z4 [N,128]
    {
        dim3 grid(128 / BN, rowBlocks);
        gemm128<false, false, false><<<grid, T>>>(z4, h3, nullptr, W4_rel, W4_root,
                                                  nullptr, NNODES, D_H, 128, 64);
    }
    out_init_kernel<<<(NNODES * D_IN + T - 1) / T, T>>>(out, b4);
    edge_agg_kernel<64><<<(NEDGES * 16 + T - 1) / T, T>>>(z4, 128, out, D_IN);
}

// round 5
// speedup vs baseline: 2.8675x; 1.8309x over previous
#include <cuda_runtime.h>
#include <cuda_bf16.h>
#include <cstdint>

#define NNODES 50000
#define NEDGES 200000
#define NGRAPH 2048
#define D_IN   64
#define D_H    1000
#define D_ENC  128

typedef __nv_bfloat16 bf16;

// ---------------- scratch (static device allocations; no cudaMalloc) --------
__device__ float g_aggx [NNODES * D_IN];
__device__ float g_aggy [NNODES * D_ENC];
__device__ float g_h2f  [NNODES * D_ENC];
__device__ float g_aggh2[NNODES * D_ENC];
__device__ float g_z2   [NNODES * 256];   // cols 0..127 rel, 128..255 root
__device__ float g_z4   [NNODES * 128];   // cols 0..63  rel, 64..127  root
__device__ float g_sums [NGRAPH * D_ENC];
__device__ float g_counts[NGRAPH];
__device__ int   g_ei32[2 * NEDGES];
__device__ int   g_batch32[NNODES];
__device__ int   g_is64;

// bf16 hi/lo operand arrays
__device__ bf16 g_x_h   [NNODES * D_IN],  g_x_l   [NNODES * D_IN];
__device__ bf16 g_aggx_h[NNODES * D_IN],  g_aggx_l[NNODES * D_IN];
__device__ bf16 g_h1_h  [(size_t)NNODES * D_H], g_h1_l[(size_t)NNODES * D_H];
__device__ bf16 g_h2_h  [NNODES * D_ENC], g_h2_l [NNODES * D_ENC];
__device__ bf16 g_ah2_h [NNODES * D_ENC], g_ah2_l[NNODES * D_ENC];
__device__ bf16 g_h3_h  [(size_t)NNODES * D_H], g_h3_l[(size_t)NNODES * D_H];
// weights (bf16 hi/lo); w2 = [W2_rel;W2_root] (256x1000), w4 = [W4_rel;W4_root] (128x1000)
__device__ bf16 g_w1r_h[D_H * D_IN],  g_w1r_l[D_H * D_IN];
__device__ bf16 g_w1o_h[D_H * D_IN],  g_w1o_l[D_H * D_IN];
__device__ bf16 g_w2_h [256 * D_H],   g_w2_l [256 * D_H];
__device__ bf16 g_w3r_h[D_H * D_ENC], g_w3r_l[D_H * D_ENC];
__device__ bf16 g_w3o_h[D_H * D_ENC], g_w3o_l[D_H * D_ENC];
__device__ bf16 g_w4_h [128 * D_H],   g_w4_l [128 * D_H];

// ---------------- helpers ----------------------------------------------------
__device__ __forceinline__ void split_bf(float v, uint16_t& h, uint16_t& l) {
    bf16 hb = __float2bfloat16(v);
    bf16 lb = __float2bfloat16(v - __bfloat162float(hb));
    h = __bfloat16_as_ushort(hb);
    l = __bfloat16_as_ushort(lb);
}
__device__ __forceinline__ void mma16816(float* d, const uint32_t* a, uint32_t b0, uint32_t b1) {
    asm volatile(
        "mma.sync.aligned.m16n8k16.row.col.f32.bf16.bf16.f32 "
        "{%0,%1,%2,%3}, {%4,%5,%6,%7}, {%8,%9}, {%0,%1,%2,%3};"
        : "+f"(d[0]), "+f"(d[1]), "+f"(d[2]), "+f"(d[3])
        : "r"(a[0]), "r"(a[1]), "r"(a[2]), "r"(a[3]), "r"(b0), "r"(b1));
}

// ---------------- dtype detection + conversion ------------------------------
__global__ void detect_kernel(const int* __restrict__ ei_raw) {
    int odd_zero = 1;
    #pragma unroll
    for (int i = 0; i < 16; ++i)
        if (ei_raw[2 * i + 1] != 0) odd_zero = 0;
    g_is64 = odd_zero;
}
__global__ void convert_kernel(const int* __restrict__ ei_raw, const int* __restrict__ batch_raw) {
    int i = blockIdx.x * blockDim.x + threadIdx.x;
    int is64 = g_is64;
    if (i < 2 * NEDGES) g_ei32[i] = is64 ? ei_raw[2 * i] : ei_raw[i];
    if (i < NNODES)     g_batch32[i] = is64 ? batch_raw[2 * i] : batch_raw[i];
}

// ---------------- utility kernels -------------------------------------------
__global__ void zero_kernel(float* p, int n) {
    for (int i = blockIdx.x * blockDim.x + threadIdx.x; i < n; i += gridDim.x * blockDim.x)
        p[i] = 0.f;
}
__global__ void split_kernel(const float* __restrict__ src, bf16* __restrict__ hi,
                             bf16* __restrict__ lo, int n) {
    for (int i = blockIdx.x * blockDim.x + threadIdx.x; i < n; i += gridDim.x * blockDim.x) {
        uint16_t h, l;
        split_bf(src[i], h, l);
        hi[i] = __ushort_as_bfloat16(h);
        lo[i] = __ushort_as_bfloat16(l);
    }
}
template <int F>
__global__ void edge_agg_kernel(const float* __restrict__ feat, int featStride,
                                float* __restrict__ out, int outStride) {
    constexpr int V = F / 4;
    int idx = blockIdx.x * blockDim.x + threadIdx.x;
    int e = idx / V;
    int f = (idx % V) * 4;
    if (e >= NEDGES) return;
    int s = g_ei32[e];
    int d = g_ei32[NEDGES + e];
    float4 v = *reinterpret_cast<const float4*>(&feat[(size_t)s * featStride + f]);
    float* o = &out[(size_t)d * outStride + f];
    atomicAdd(o + 0, v.x); atomicAdd(o + 1, v.y);
    atomicAdd(o + 2, v.z); atomicAdd(o + 3, v.w);
}
__global__ void combine_h2_kernel(const float* __restrict__ b2) {
    int idx = blockIdx.x * blockDim.x + threadIdx.x;
    if (idx >= NNODES * D_ENC) return;
    int i = idx >> 7, f = idx & 127;
    float v = fmaxf(g_aggy[idx] + g_z2[(size_t)i * 256 + 128 + f] + b2[f], 0.f);
    g_h2f[idx] = v;
    uint16_t h, l; split_bf(v, h, l);
    g_h2_h[idx] = __ushort_as_bfloat16(h);
    g_h2_l[idx] = __ushort_as_bfloat16(l);
}
__global__ void pool_kernel() {
    int idx = blockIdx.x * blockDim.x + threadIdx.x;
    if (idx >= NNODES * D_ENC) return;
    int i = idx >> 7, f = idx & 127;
    int b = g_batch32[i];
    atomicAdd(&g_sums[b * D_ENC + f], g_h2f[idx]);
    if (f == 0) atomicAdd(&g_counts[b], 1.f);
}
__global__ void encoded_kernel(float* __restrict__ enc) {
    int idx = blockIdx.x * blockDim.x + threadIdx.x;
    if (idx >= NGRAPH * D_ENC) return;
    int g = idx >> 7;
    enc[idx] = g_sums[idx] / fmaxf(g_counts[g], 1.f);
}
__global__ void out_init_kernel(float* __restrict__ out, const float* __restrict__ b4) {
    int idx = blockIdx.x * blockDim.x + threadIdx.x;
    if (idx >= NNODES * D_IN) return;
    int i = idx >> 6, f = idx & 63;
    out[idx] = g_z4[(size_t)i * 128 + 64 + f] + b4[f];
}

// ---------------- mma.sync bf16x3 GEMM ---------------------------------------
// C[M,O] = sum_sides A_s[M,K] @ W_s[O,K]^T, A/W as bf16 hi/lo; fp32 accum.
// block 128x128; 8 warps (4m x 2n); warp tile 32x64; m16n8k16 fragments.
#define SSTRIDE 144          // bytes per SMEM row (72 bf16)
#define ATILE   18432        // 128 * 144

template <bool DUAL_A, bool RELU, bool BIAS, bool BF16OUT>
__global__ void __launch_bounds__(256, 2) mmagemm(
    float* __restrict__ Cf, bf16* __restrict__ Ch, bf16* __restrict__ Cl,
    const bf16* __restrict__ A1h, const bf16* __restrict__ A1l,
    const bf16* __restrict__ A2h, const bf16* __restrict__ A2l,
    const bf16* __restrict__ B1h, const bf16* __restrict__ B1l,
    const bf16* __restrict__ B2h, const bf16* __restrict__ B2l,
    const float* __restrict__ bias, int M, int K, int O) {

    extern __shared__ char sm[];
    char* sAh = sm;
    char* sAl = sm + ATILE;
    char* sWh = sm + 2 * ATILE;
    char* sWl = sm + 3 * ATILE;

    const int tid = threadIdx.x;
    const int wid = tid >> 5, lane = tid & 31;
    const int g = lane >> 2, t = lane & 3;
    const int warpM = (wid & 3) * 32, warpN = (wid >> 2) * 64;
    const int rowBase = blockIdx.y * 128, colBase = blockIdx.x * 128;

    float acc[2][8][4];
    #pragma unroll
    for (int a = 0; a < 2; ++a)
        #pragma unroll
        for (int b = 0; b < 8; ++b)
            #pragma unroll
            for (int c = 0; c < 4; ++c) acc[a][b][c] = 0.f;

    const int KC = (K + 63) >> 6;
    const int S = DUAL_A ? 2 : 1;

    for (int s = 0; s < S; ++s) {
        const bf16* Ah = (DUAL_A && s) ? A2h : A1h;
        const bf16* Al = (DUAL_A && s) ? A2l : A1l;
        const bf16* Wh = (DUAL_A && s) ? B2h : B1h;
        const bf16* Wl = (DUAL_A && s) ? B2l : B1l;
        for (int c = 0; c < KC; ++c) {
            const int k0 = c << 6;
            __syncthreads();
            // ---- load A/W tiles (128 rows x 64 bf16 each, stride 72) ----
            #pragma unroll
            for (int i = 0; i < 4; ++i) {
                int sid = tid + i * 256;
                int r = sid >> 3, seg = sid & 7;
                int gk = k0 + seg * 8;
                bool kok = (gk + 8 <= K);
                uint4 z = make_uint4(0, 0, 0, 0);
                uint4 vh = z, vl = z, wh = z, wl = z;
                int gr = rowBase + r;
                if (gr < M && kok) {
                    size_t off = (size_t)gr * K + gk;
                    vh = *reinterpret_cast<const uint4*>(Ah + off);
                    vl = *reinterpret_cast<const uint4*>(Al + off);
                }
                int gw = colBase + r;
                if (gw < O && kok) {
                    size_t off = (size_t)gw * K + gk;
                    wh = *reinterpret_cast<const uint4*>(Wh + off);
                    wl = *reinterpret_cast<const uint4*>(Wl + off);
                }
                int so = r * SSTRIDE + seg * 16;
                *reinterpret_cast<uint4*>(sAh + so) = vh;
                *reinterpret_cast<uint4*>(sAl + so) = vl;
                *reinterpret_cast<uint4*>(sWh + so) = wh;
                *reinterpret_cast<uint4*>(sWl + so) = wl;
            }
            __syncthreads();

            // ---- compute: 4 k16 steps ----
            #pragma unroll
            for (int ks = 0; ks < 4; ++ks) {
                uint32_t ah[2][4], al[2][4];
                #pragma unroll
                for (int mi = 0; mi < 2; ++mi) {
                    int r = warpM + mi * 16 + g;
                    int o0 = r * SSTRIDE + ks * 32 + t * 4;
                    ah[mi][0] = *reinterpret_cast<const uint32_t*>(sAh + o0);
                    ah[mi][1] = *reinterpret_cast<const uint32_t*>(sAh + o0 + 8 * SSTRIDE);
                    ah[mi][2] = *reinterpret_cast<const uint32_t*>(sAh + o0 + 16);
                    ah[mi][3] = *reinterpret_cast<const uint32_t*>(sAh + o0 + 8 * SSTRIDE + 16);
                    al[mi][0] = *reinterpret_cast<const uint32_t*>(sAl + o0);
                    al[mi][1] = *reinterpret_cast<const uint32_t*>(sAl + o0 + 8 * SSTRIDE);
                    al[mi][2] = *reinterpret_cast<const uint32_t*>(sAl + o0 + 16);
                    al[mi][3] = *reinterpret_cast<const uint32_t*>(sAl + o0 + 8 * SSTRIDE + 16);
                }
                #pragma unroll
                for (int ni = 0; ni < 8; ++ni) {
                    int n = warpN + ni * 8 + g;
                    int o0 = n * SSTRIDE + ks * 32 + t * 4;
                    uint32_t b0h = *reinterpret_cast<const uint32_t*>(sWh + o0);
                    uint32_t b1h = *reinterpret_cast<const uint32_t*>(sWh + o0 + 16);
                    uint32_t b0l = *reinterpret_cast<const uint32_t*>(sWl + o0);
                    uint32_t b1l = *reinterpret_cast<const uint32_t*>(sWl + o0 + 16);
                    #pragma unroll
                    for (int mi = 0; mi < 2; ++mi) {
                        mma16816(acc[mi][ni], ah[mi], b0h, b1h);
                        mma16816(acc[mi][ni], al[mi], b0h, b1h);
                        mma16816(acc[mi][ni], ah[mi], b0l, b1l);
                    }
                }
            }
        }
    }

    // ---- epilogue ----
    #pragma unroll
    for (int mi = 0; mi < 2; ++mi) {
        #pragma unroll
        for (int half = 0; half < 2; ++half) {
            int row = rowBase + warpM + mi * 16 + g + half * 8;
            if (row >= M) continue;
            #pragma unroll
            for (int ni = 0; ni < 8; ++ni) {
                int col = colBase + warpN + ni * 8 + 2 * t;
                if (col >= O) continue;
                float v0 = acc[mi][ni][half * 2 + 0];
                float v1 = acc[mi][ni][half * 2 + 1];
                if (BIAS) { v0 += bias[col]; if (col + 1 < O) v1 += bias[col + 1]; }
                if (RELU) { v0 = fmaxf(v0, 0.f); v1 = fmaxf(v1, 0.f); }
                bool pair = (col + 1 < O);
                if (BF16OUT) {
                    uint16_t h0, l0, h1, l1;
                    split_bf(v0, h0, l0);
                    split_bf(v1, h1, l1);
                    size_t o = (size_t)row * O + col;
                    if (pair) {
                        *reinterpret_cast<uint32_t*>(&Ch[o]) = (uint32_t)h0 | ((uint32_t)h1 << 16);
                        *reinterpret_cast<uint32_t*>(&Cl[o]) = (uint32_t)l0 | ((uint32_t)l1 << 16);
                    } else {
                        Ch[o] = __ushort_as_bfloat16(h0);
                        Cl[o] = __ushort_as_bfloat16(l0);
                    }
                } else {
                    size_t o = (size_t)row * O + col;
                    if (pair) {
                        *reinterpret_cast<float2*>(&Cf[o]) = make_float2(v0, v1);
                    } else {
                        Cf[o] = v0;
                    }
                }
            }
        }
    }
}

// ---------------- launch ----------------------------------------------------
extern "C" void kernel_launch(void* const* d_in, const int* in_sizes, int n_in,
                              void* d_out, int out_size) {
    const float* x         = (const float*)d_in[0];
    const int*   ei_raw    = (const int*)d_in[1];
    const int*   batch_raw = (const int*)d_in[2];
    const float* W1_rel = (const float*)d_in[3];
    const float* b1     = (const float*)d_in[4];
    const float* W1_root= (const float*)d_in[5];
    const float* W2_rel = (const float*)d_in[6];
    const float* b2     = (const float*)d_in[7];
    const float* W2_root= (const float*)d_in[8];
    const float* W3_rel = (const float*)d_in[9];
    const float* b3     = (const float*)d_in[10];
    const float* W3_root= (const float*)d_in[11];
    const float* W4_rel = (const float*)d_in[12];
    const float* b4     = (const float*)d_in[13];
    const float* W4_root= (const float*)d_in[14];

    float* out = (float*)d_out;
    float* enc = out + (size_t)NNODES * D_IN;

    float *aggx, *aggy, *h2f, *aggh2, *z2, *z4, *sums, *counts;
    bf16 *x_h, *x_l, *aggx_h, *aggx_l, *h1_h, *h1_l, *h2_h, *h2_l, *ah2_h, *ah2_l, *h3_h, *h3_l;
    bf16 *w1r_h, *w1r_l, *w1o_h, *w1o_l, *w2_h, *w2_l, *w3r_h, *w3r_l, *w3o_h, *w3o_l, *w4_h, *w4_l;
    cudaGetSymbolAddress((void**)&aggx, g_aggx);   cudaGetSymbolAddress((void**)&aggy, g_aggy);
    cudaGetSymbolAddress((void**)&h2f, g_h2f);     cudaGetSymbolAddress((void**)&aggh2, g_aggh2);
    cudaGetSymbolAddress((void**)&z2, g_z2);       cudaGetSymbolAddress((void**)&z4, g_z4);
    cudaGetSymbolAddress((void**)&sums, g_sums);   cudaGetSymbolAddress((void**)&counts, g_counts);
    cudaGetSymbolAddress((void**)&x_h, g_x_h);     cudaGetSymbolAddress((void**)&x_l, g_x_l);
    cudaGetSymbolAddress((void**)&aggx_h, g_aggx_h); cudaGetSymbolAddress((void**)&aggx_l, g_aggx_l);
    cudaGetSymbolAddress((void**)&h1_h, g_h1_h);   cudaGetSymbolAddress((void**)&h1_l, g_h1_l);
    cudaGetSymbolAddress((void**)&h2_h, g_h2_h);   cudaGetSymbolAddress((void**)&h2_l, g_h2_l);
    cudaGetSymbolAddress((void**)&ah2_h, g_ah2_h); cudaGetSymbolAddress((void**)&ah2_l, g_ah2_l);
    cudaGetSymbolAddress((void**)&h3_h, g_h3_h);   cudaGetSymbolAddress((void**)&h3_l, g_h3_l);
    cudaGetSymbolAddress((void**)&w1r_h, g_w1r_h); cudaGetSymbolAddress((void**)&w1r_l, g_w1r_l);
    cudaGetSymbolAddress((void**)&w1o_h, g_w1o_h); cudaGetSymbolAddress((void**)&w1o_l, g_w1o_l);
    cudaGetSymbolAddress((void**)&w2_h, g_w2_h);   cudaGetSymbolAddress((void**)&w2_l, g_w2_l);
    cudaGetSymbolAddress((void**)&w3r_h, g_w3r_h); cudaGetSymbolAddress((void**)&w3r_l, g_w3r_l);
    cudaGetSymbolAddress((void**)&w3o_h, g_w3o_h); cudaGetSymbolAddress((void**)&w3o_l, g_w3o_l);
    cudaGetSymbolAddress((void**)&w4_h, g_w4_h);   cudaGetSymbolAddress((void**)&w4_l, g_w4_l);

    const int T = 256;
    const int MB = (NNODES + 127) / 128;   // 391
    constexpr int SMEM = 4 * ATILE;        // 73728

    cudaFuncSetAttribute(mmagemm<true,  true,  true,  true >, cudaFuncAttributeMaxDynamicSharedMemorySize, SMEM);
    cudaFuncSetAttribute(mmagemm<false, false, false, false>, cudaFuncAttributeMaxDynamicSharedMemorySize, SMEM);

    // ---- index dtype detect + convert
    detect_kernel<<<1, 1>>>(ei_raw);
    convert_kernel<<<(2 * NEDGES + T - 1) / T, T>>>(ei_raw, batch_raw);

    // ---- weight + x splits
    split_kernel<<<128, T>>>(W1_rel,  w1r_h, w1r_l, D_H * D_IN);
    split_kernel<<<128, T>>>(W1_root, w1o_h, w1o_l, D_H * D_IN);
    split_kernel<<<256, T>>>(W2_rel,  w2_h,           w2_l,           128 * D_H);
    split_kernel<<<256, T>>>(W2_root, w2_h + 128*D_H, w2_l + 128*D_H, 128 * D_H);
    split_kernel<<<256, T>>>(W3_rel,  w3r_h, w3r_l, D_H * D_ENC);
    split_kernel<<<256, T>>>(W3_root, w3o_h, w3o_l, D_H * D_ENC);
    split_kernel<<<128, T>>>(W4_rel,  w4_h,          w4_l,          64 * D_H);
    split_kernel<<<128, T>>>(W4_root, w4_h + 64*D_H, w4_l + 64*D_H, 64 * D_H);
    split_kernel<<<1024, T>>>(x, x_h, x_l, NNODES * D_IN);

    // ---- L1: agg(x) then dual-A MMA -> h1 (bf16 hi/lo, relu, bias)
    zero_kernel<<<1024, T>>>(aggx, NNODES * D_IN);
    edge_agg_kernel<64><<<(NEDGES * 16 + T - 1) / T, T>>>(x, D_IN, aggx, D_IN);
    split_kernel<<<1024, T>>>(aggx, aggx_h, aggx_l, NNODES * D_IN);
    {
        dim3 grid((D_H + 127) / 128, MB);
        mmagemm<true, true, true, true><<<grid, T, SMEM>>>(
            nullptr, h1_h, h1_l,
            aggx_h, aggx_l, x_h, x_l,
            w1r_h, w1r_l, w1o_h, w1o_l,
            b1, NNODES, D_IN, D_H);
    }

    // ---- L2: single-A MMA (K=1000, O=256 cat) -> z2 fp32
    {
        dim3 grid(2, MB);
        mmagemm<false, false, false, false><<<grid, T, SMEM>>>(
            z2, nullptr, nullptr,
            h1_h, h1_l, nullptr, nullptr,
            w2_h, w2_l, nullptr, nullptr,
            nullptr, NNODES, D_H, 256);
    }
    zero_kernel<<<1024, T>>>(aggy, NNODES * D_ENC);
    edge_agg_kernel<128><<<(NEDGES * 32 + T - 1) / T, T>>>(z2, 256, aggy, D_ENC);
    combine_h2_kernel<<<(NNODES * D_ENC + T - 1) / T, T>>>(b2);

    // ---- pooling -> encoded
    zero_kernel<<<256, T>>>(sums, NGRAPH * D_ENC);
    zero_kernel<<<8, T>>>(counts, NGRAPH);
    pool_kernel<<<(NNODES * D_ENC + T - 1) / T, T>>>();
    encoded_kernel<<<(NGRAPH * D_ENC + T - 1) / T, T>>>(enc);

    // ---- L3: agg(h2) then dual-A MMA -> h3 (bf16 hi/lo, relu, bias)
    zero_kernel<<<1024, T>>>(aggh2, NNODES * D_ENC);
    edge_agg_kernel<128><<<(NEDGES * 32 + T - 1) / T, T>>>(h2f, D_ENC, aggh2, D_ENC);
    split_kernel<<<1024, T>>>(aggh2, ah2_h, ah2_l, NNODES * D_ENC);
    {
        dim3 grid((D_H + 127) / 128, MB);
        mmagemm<true, true, true, true><<<grid, T, SMEM>>>(
            nullptr, h3_h, h3_l,
            ah2_h, ah2_l, h2_h, h2_l,
            w3r_h, w3r_l, w3o_h, w3o_l,
            b3, NNODES, D_ENC, D_H);
    }

    // ---- L4: single-A MMA (K=1000, O=128 cat) -> z4 fp32
    {
        dim3 grid(1, MB);
        mmagemm<false, false, false, false><<<grid, T, SMEM>>>(
            z4, nullptr, nullptr,
            h3_h, h3_l, nullptr, nullptr,
            w4_h, w4_l, nullptr, nullptr,
            nullptr, NNODES, D_H, 128);
    }
    out_init_kernel<<<(NNODES * D_IN + T - 1) / T, T>>>(out, b4);
    edge_agg_kernel<64><<<(NEDGES * 16 + T - 1) / T, T>>>(z4, 128, out, D_IN);
}

// round 6
// speedup vs baseline: 3.1505x; 1.0987x over previous
#include <cuda_runtime.h>
#include <cuda_bf16.h>
#include <cstdint>

#define NNODES 50000
#define NEDGES 200000
#define NGRAPH 2048
#define D_IN   64
#define D_H    1000
#define D_ENC  128

typedef __nv_bfloat16 bf16;

// ---------------- scratch (static device allocations; no cudaMalloc) --------
__device__ float g_aggx [NNODES * D_IN];
__device__ float g_aggy [NNODES * D_ENC];
__device__ float g_h2f  [NNODES * D_ENC];
__device__ float g_aggh2[NNODES * D_ENC];
__device__ float g_z2   [NNODES * 256];   // cols 0..127 rel, 128..255 root
__device__ float g_z4   [NNODES * 128];   // cols 0..63  rel, 64..127  root
__device__ float g_sums [NGRAPH * D_ENC];
__device__ float g_counts[NGRAPH];
__device__ int   g_ei32[2 * NEDGES];
__device__ int   g_batch32[NNODES];
__device__ int   g_is64;

__device__ __align__(16) bf16 g_x_h   [NNODES * D_IN],  g_x_l   [NNODES * D_IN];
__device__ __align__(16) bf16 g_aggx_h[NNODES * D_IN],  g_aggx_l[NNODES * D_IN];
__device__ __align__(16) bf16 g_h1_h  [(size_t)NNODES * D_H], g_h1_l[(size_t)NNODES * D_H];
__device__ __align__(16) bf16 g_h2_h  [NNODES * D_ENC], g_h2_l [NNODES * D_ENC];
__device__ __align__(16) bf16 g_ah2_h [NNODES * D_ENC], g_ah2_l[NNODES * D_ENC];
__device__ __align__(16) bf16 g_h3_h  [(size_t)NNODES * D_H], g_h3_l[(size_t)NNODES * D_H];
__device__ __align__(16) bf16 g_w1r_h[D_H * D_IN],  g_w1r_l[D_H * D_IN];
__device__ __align__(16) bf16 g_w1o_h[D_H * D_IN],  g_w1o_l[D_H * D_IN];
__device__ __align__(16) bf16 g_w2_h [256 * D_H],   g_w2_l [256 * D_H];
__device__ __align__(16) bf16 g_w3r_h[D_H * D_ENC], g_w3r_l[D_H * D_ENC];
__device__ __align__(16) bf16 g_w3o_h[D_H * D_ENC], g_w3o_l[D_H * D_ENC];
__device__ __align__(16) bf16 g_w4_h [128 * D_H],   g_w4_l [128 * D_H];

// ---------------- helpers ----------------------------------------------------
__device__ __forceinline__ void split_bf(float v, uint16_t& h, uint16_t& l) {
    bf16 hb = __float2bfloat16(v);
    bf16 lb = __float2bfloat16(v - __bfloat162float(hb));
    h = __bfloat16_as_ushort(hb);
    l = __bfloat16_as_ushort(lb);
}
__device__ __forceinline__ void mma16816(float* d, const uint32_t* a, uint32_t b0, uint32_t b1) {
    asm volatile(
        "mma.sync.aligned.m16n8k16.row.col.f32.bf16.bf16.f32 "
        "{%0,%1,%2,%3}, {%4,%5,%6,%7}, {%8,%9}, {%0,%1,%2,%3};"
        : "+f"(d[0]), "+f"(d[1]), "+f"(d[2]), "+f"(d[3])
        : "r"(a[0]), "r"(a[1]), "r"(a[2]), "r"(a[3]), "r"(b0), "r"(b1));
}
__device__ __forceinline__ uint32_t cvta_s(const void* p) {
    uint32_t a;
    asm("{ .reg .u64 t; cvta.to.shared.u64 t, %1; cvt.u32.u64 %0, t; }" : "=r"(a) : "l"(p));
    return a;
}
#define LDMX4(r, a) \
    asm volatile("ldmatrix.sync.aligned.m8n8.x4.shared.b16 {%0,%1,%2,%3}, [%4];" \
        : "=r"((r)[0]), "=r"((r)[1]), "=r"((r)[2]), "=r"((r)[3]) : "r"(a))

// ---------------- dtype detection + conversion ------------------------------
__global__ void detect_kernel(const int* __restrict__ ei_raw) {
    int odd_zero = 1;
    #pragma unroll
    for (int i = 0; i < 16; ++i)
        if (ei_raw[2 * i + 1] != 0) odd_zero = 0;
    g_is64 = odd_zero;
}
__global__ void convert_kernel(const int* __restrict__ ei_raw, const int* __restrict__ batch_raw) {
    int i = blockIdx.x * blockDim.x + threadIdx.x;
    int is64 = g_is64;
    if (i < 2 * NEDGES) g_ei32[i] = is64 ? ei_raw[2 * i] : ei_raw[i];
    if (i < NNODES)     g_batch32[i] = is64 ? batch_raw[2 * i] : batch_raw[i];
}

// ---------------- merged utility kernels -------------------------------------
__global__ void zero_all_kernel() {
    for (int i = blockIdx.x * blockDim.x + threadIdx.x; i < NNODES * D_ENC;
         i += gridDim.x * blockDim.x) {
        g_aggy[i] = 0.f;
        g_aggh2[i] = 0.f;
        if (i < NNODES * D_IN) g_aggx[i] = 0.f;
        if (i < NGRAPH * D_ENC) g_sums[i] = 0.f;
        if (i < NGRAPH) g_counts[i] = 0.f;
    }
}
// split all weights + x in one launch
__global__ void split_static_kernel(
    const float* __restrict__ w1r, const float* __restrict__ w1o,
    const float* __restrict__ w2r, const float* __restrict__ w2o,
    const float* __restrict__ w3r, const float* __restrict__ w3o,
    const float* __restrict__ w4r, const float* __restrict__ w4o,
    const float* __restrict__ x) {
    const int N1 = D_H * D_IN;      // 64000
    const int N2 = 128 * D_H;       // 128000
    const int N3 = D_H * D_ENC;     // 128000
    const int N4 = 64 * D_H;        // 64000
    const int TOT = 2 * N1 + 2 * N2 + 2 * N3 + 2 * N4 + NNODES * D_IN;
    for (int i = blockIdx.x * blockDim.x + threadIdx.x; i < TOT;
         i += gridDim.x * blockDim.x) {
        float v; bf16 *dh, *dl; int j = i;
        if (j < N1)            { v = w1r[j]; dh = g_w1r_h + j; dl = g_w1r_l + j; }
        else if ((j -= N1) < N1) { v = w1o[j]; dh = g_w1o_h + j; dl = g_w1o_l + j; }
        else if ((j -= N1) < N2) { v = w2r[j]; dh = g_w2_h + j; dl = g_w2_l + j; }
        else if ((j -= N2) < N2) { v = w2o[j]; dh = g_w2_h + N2 + j; dl = g_w2_l + N2 + j; }
        else if ((j -= N2) < N3) { v = w3r[j]; dh = g_w3r_h + j; dl = g_w3r_l + j; }
        else if ((j -= N3) < N3) { v = w3o[j]; dh = g_w3o_h + j; dl = g_w3o_l + j; }
        else if ((j -= N3) < N4) { v = w4r[j]; dh = g_w4_h + j; dl = g_w4_l + j; }
        else if ((j -= N4) < N4) { v = w4o[j]; dh = g_w4_h + N4 + j; dl = g_w4_l + N4 + j; }
        else { j -= N4;            v = x[j];   dh = g_x_h + j;  dl = g_x_l + j; }
        uint16_t h, l; split_bf(v, h, l);
        *dh = __ushort_as_bfloat16(h);
        *dl = __ushort_as_bfloat16(l);
    }
}
__global__ void split_kernel(const float* __restrict__ src, bf16* __restrict__ hi,
                             bf16* __restrict__ lo, int n) {
    for (int i = blockIdx.x * blockDim.x + threadIdx.x; i < n; i += gridDim.x * blockDim.x) {
        uint16_t h, l;
        split_bf(src[i], h, l);
        hi[i] = __ushort_as_bfloat16(h);
        lo[i] = __ushort_as_bfloat16(l);
    }
}
template <int F>
__global__ void edge_agg_kernel(const float* __restrict__ feat, int featStride,
                                float* __restrict__ out, int outStride) {
    constexpr int V = F / 4;
    int idx = blockIdx.x * blockDim.x + threadIdx.x;
    int e = idx / V;
    int f = (idx % V) * 4;
    if (e >= NEDGES) return;
    int s = g_ei32[e];
    int d = g_ei32[NEDGES + e];
    float4 v = *reinterpret_cast<const float4*>(&feat[(size_t)s * featStride + f]);
    float* o = &out[(size_t)d * outStride + f];
    atomicAdd(o + 0, v.x); atomicAdd(o + 1, v.y);
    atomicAdd(o + 2, v.z); atomicAdd(o + 3, v.w);
}
// fused: h2 = relu(aggy + z2_root + b2); write fp32 + hi/lo; pool into sums/counts
__global__ void combine_pool_kernel(const float* __restrict__ b2) {
    int idx = blockIdx.x * blockDim.x + threadIdx.x;
    if (idx >= NNODES * D_ENC) return;
    int i = idx >> 7, f = idx & 127;
    float v = fmaxf(g_aggy[idx] + g_z2[(size_t)i * 256 + 128 + f] + b2[f], 0.f);
    g_h2f[idx] = v;
    uint16_t h, l; split_bf(v, h, l);
    g_h2_h[idx] = __ushort_as_bfloat16(h);
    g_h2_l[idx] = __ushort_as_bfloat16(l);
    int b = g_batch32[i];
    atomicAdd(&g_sums[b * D_ENC + f], v);
    if (f == 0) atomicAdd(&g_counts[b], 1.f);
}
__global__ void encoded_kernel(float* __restrict__ enc) {
    int idx = blockIdx.x * blockDim.x + threadIdx.x;
    if (idx >= NGRAPH * D_ENC) return;
    int g = idx >> 7;
    enc[idx] = g_sums[idx] / fmaxf(g_counts[g], 1.f);
}
__global__ void out_init_kernel(float* __restrict__ out, const float* __restrict__ b4) {
    int idx = blockIdx.x * blockDim.x + threadIdx.x;
    if (idx >= NNODES * D_IN) return;
    int i = idx >> 6, f = idx & 63;
    out[idx] = g_z4[(size_t)i * 128 + 64 + f] + b4[f];
}

// ---------------- pipelined mma.sync bf16x3 GEMM -----------------------------
// C[M,O] = sum_sides A_s[M,K] @ W_s[O,K]^T; A/W as bf16 hi/lo; fp32 accum.
// block 128x128; 8 warps (4m x 2n); warp tile 32x64.
// K-chunk 32, 2-stage cp.async pipeline, ldmatrix.x4 fragment loads.
#define CHUNK 32
#define SROW  80                  // bytes per SMEM row (32 bf16 + 16B pad)
#define GTILE (128 * SROW)        // 10240
#define GSTAGE (4 * GTILE)        // 40960 (Ah, Al, Wh, Wl)

template <bool DUAL_A, bool RELU, bool BIAS, bool BF16OUT>
__global__ void __launch_bounds__(256, 2) mmagemm(
    float* __restrict__ Cf, bf16* __restrict__ Ch, bf16* __restrict__ Cl,
    const bf16* __restrict__ A1h, const bf16* __restrict__ A1l,
    const bf16* __restrict__ A2h, const bf16* __restrict__ A2l,
    const bf16* __restrict__ B1h, const bf16* __restrict__ B1l,
    const bf16* __restrict__ B2h, const bf16* __restrict__ B2l,
    const float* __restrict__ bias, int M, int K, int O) {

    extern __shared__ char smraw[];
    const uint32_t smemBase = cvta_s(smraw);

    const int tid = threadIdx.x;
    const int wid = tid >> 5, lane = tid & 31;
    const int g = lane >> 2, t = lane & 3;
    const int warpM = (wid & 3) * 32, warpN = (wid >> 2) * 64;
    const int rowBase = blockIdx.y * 128, colBase = blockIdx.x * 128;

    // ldmatrix per-lane offsets
    const int laneRowA = (lane & 7) + ((lane & 8) ? 8 : 0);
    const int aK = (lane & 16) ? 16 : 0;
    const int laneRowW = (lane & 7) + ((lane & 16) ? 8 : 0);
    const int wK = (lane & 8) ? 16 : 0;
    uint32_t aoff[2], woff[4];
    #pragma unroll
    for (int mi = 0; mi < 2; ++mi)
        aoff[mi] = (uint32_t)((warpM + mi * 16 + laneRowA) * SROW + aK);
    #pragma unroll
    for (int p = 0; p < 4; ++p)
        woff[p] = (uint32_t)((warpN + p * 16 + laneRowW) * SROW + wK);

    float acc[2][8][4];
    #pragma unroll
    for (int a = 0; a < 2; ++a)
        #pragma unroll
        for (int b = 0; b < 8; ++b)
            #pragma unroll
            for (int c = 0; c < 4; ++c) acc[a][b][c] = 0.f;

    const int KC = (K + CHUNK - 1) / CHUNK;
    const int C = (DUAL_A ? 2 : 1) * KC;

    auto loadChunk = [&](int i, int stage) {
        int sIdx = DUAL_A ? (i / KC) : 0;
        int c = i - sIdx * KC;
        int k0 = c * CHUNK;
        const bf16* Ah = (DUAL_A && sIdx) ? A2h : A1h;
        const bf16* Al = (DUAL_A && sIdx) ? A2l : A1l;
        const bf16* Wh = (DUAL_A && sIdx) ? B2h : B1h;
        const bf16* Wl = (DUAL_A && sIdx) ? B2l : B1l;
        uint32_t sb = smemBase + stage * GSTAGE;
        #pragma unroll
        for (int j = 0; j < 8; ++j) {
            int idx = tid + j * 256;
            int tile = idx >> 9;          // 0..3
            int r = (idx >> 2) & 127;
            int sg = idx & 3;
            int gk = k0 + sg * 8;
            const bf16* src;
            int ok;
            if (tile < 2) {
                int gr = rowBase + r;
                ok = (gr < M) && (gk + 8 <= K);
                const bf16* base = tile ? Al : Ah;
                src = ok ? base + (size_t)gr * K + gk : base;
            } else {
                int gw = colBase + r;
                ok = (gw < O) && (gk + 8 <= K);
                const bf16* base = (tile == 2) ? Wh : Wl;
                src = ok ? base + (size_t)gw * K + gk : base;
            }
            uint32_t dst = sb + tile * GTILE + (uint32_t)(r * SROW + sg * 16);
            int sz = ok ? 16 : 0;
            asm volatile("cp.async.cg.shared.global [%0], [%1], 16, %2;"
                         :: "r"(dst), "l"(src), "r"(sz) : "memory");
        }
        asm volatile("cp.async.commit_group;" ::: "memory");
    };

    auto computeChunk = [&](int stage) {
        uint32_t sb = smemBase + stage * GSTAGE;
        uint32_t bAh = sb, bAl = sb + GTILE, bWh = sb + 2 * GTILE, bWl = sb + 3 * GTILE;
        #pragma unroll
        for (int ks = 0; ks < 2; ++ks) {
            uint32_t koff = ks * 32;
            uint32_t ah[2][4], al[2][4];
            #pragma unroll
            for (int mi = 0; mi < 2; ++mi) {
                LDMX4(ah[mi], bAh + aoff[mi] + koff);
                LDMX4(al[mi], bAl + aoff[mi] + koff);
            }
            #pragma unroll
            for (int p = 0; p < 4; ++p) {
                uint32_t w[4];
                LDMX4(w, bWh + woff[p] + koff);
                // w = {b0(ni=2p), b1(2p), b0(2p+1), b1(2p+1)}
                mma16816(acc[0][2 * p],     ah[0], w[0], w[1]);
                mma16816(acc[1][2 * p],     ah[1], w[0], w[1]);
                mma16816(acc[0][2 * p + 1], ah[0], w[2], w[3]);
                mma16816(acc[1][2 * p + 1], ah[1], w[2], w[3]);
                mma16816(acc[0][2 * p],     al[0], w[0], w[1]);
                mma16816(acc[1][2 * p],     al[1], w[0], w[1]);
                mma16816(acc[0][2 * p + 1], al[0], w[2], w[3]);
                mma16816(acc[1][2 * p + 1], al[1], w[2], w[3]);
                uint32_t wl[4];
                LDMX4(wl, bWl + woff[p] + koff);
                mma16816(acc[0][2 * p],     ah[0], wl[0], wl[1]);
                mma16816(acc[1][2 * p],     ah[1], wl[0], wl[1]);
                mma16816(acc[0][2 * p + 1], ah[0], wl[2], wl[3]);
                mma16816(acc[1][2 * p + 1], ah[1], wl[2], wl[3]);
            }
        }
    };

    loadChunk(0, 0);
    for (int c = 0; c < C; ++c) {
        if (c + 1 < C) {
            loadChunk(c + 1, (c + 1) & 1);
            asm volatile("cp.async.wait_group 1;" ::: "memory");
        } else {
            asm volatile("cp.async.wait_group 0;" ::: "memory");
        }
        __syncthreads();
        computeChunk(c & 1);
        __syncthreads();
    }

    // ---- epilogue ----
    #pragma unroll
    for (int mi = 0; mi < 2; ++mi) {
        #pragma unroll
        for (int half = 0; half < 2; ++half) {
            int row = rowBase + warpM + mi * 16 + g + half * 8;
            if (row >= M) continue;
            #pragma unroll
            for (int ni = 0; ni < 8; ++ni) {
                int col = colBase + warpN + ni * 8 + 2 * t;
                if (col >= O) continue;
                float v0 = acc[mi][ni][half * 2 + 0];
                float v1 = acc[mi][ni][half * 2 + 1];
                if (BIAS) { v0 += bias[col]; if (col + 1 < O) v1 += bias[col + 1]; }
                if (RELU) { v0 = fmaxf(v0, 0.f); v1 = fmaxf(v1, 0.f); }
                bool pair = (col + 1 < O);
                size_t o = (size_t)row * O + col;
                if (BF16OUT) {
                    uint16_t h0, l0, h1, l1;
                    split_bf(v0, h0, l0);
                    split_bf(v1, h1, l1);
                    if (pair) {
                        *reinterpret_cast<uint32_t*>(&Ch[o]) = (uint32_t)h0 | ((uint32_t)h1 << 16);
                        *reinterpret_cast<uint32_t*>(&Cl[o]) = (uint32_t)l0 | ((uint32_t)l1 << 16);
                    } else {
                        Ch[o] = __ushort_as_bfloat16(h0);
                        Cl[o] = __ushort_as_bfloat16(l0);
                    }
                } else {
                    if (pair) *reinterpret_cast<float2*>(&Cf[o]) = make_float2(v0, v1);
                    else      Cf[o] = v0;
                }
            }
        }
    }
}

// ---------------- launch ----------------------------------------------------
extern "C" void kernel_launch(void* const* d_in, const int* in_sizes, int n_in,
                              void* d_out, int out_size) {
    const float* x         = (const float*)d_in[0];
    const int*   ei_raw    = (const int*)d_in[1];
    const int*   batch_raw = (const int*)d_in[2];
    const float* W1_rel = (const float*)d_in[3];
    const float* b1     = (const float*)d_in[4];
    const float* W1_root= (const float*)d_in[5];
    const float* W2_rel = (const float*)d_in[6];
    const float* b2     = (const float*)d_in[7];
    const float* W2_root= (const float*)d_in[8];
    const float* W3_rel = (const float*)d_in[9];
    const float* b3     = (const float*)d_in[10];
    const float* W3_root= (const float*)d_in[11];
    const float* W4_rel = (const float*)d_in[12];
    const float* b4     = (const float*)d_in[13];
    const float* W4_root= (const float*)d_in[14];

    float* out = (float*)d_out;
    float* enc = out + (size_t)NNODES * D_IN;

    float *aggx, *aggy, *h2f, *aggh2, *z2, *z4;
    bf16 *x_h, *x_l, *aggx_h, *aggx_l, *h1_h, *h1_l, *h2_h, *h2_l, *ah2_h, *ah2_l, *h3_h, *h3_l;
    bf16 *w1r_h, *w1r_l, *w1o_h, *w1o_l, *w2_h, *w2_l, *w3r_h, *w3r_l, *w3o_h, *w3o_l, *w4_h, *w4_l;
    cudaGetSymbolAddress((void**)&aggx, g_aggx);   cudaGetSymbolAddress((void**)&aggy, g_aggy);
    cudaGetSymbolAddress((void**)&h2f, g_h2f);     cudaGetSymbolAddress((void**)&aggh2, g_aggh2);
    cudaGetSymbolAddress((void**)&z2, g_z2);       cudaGetSymbolAddress((void**)&z4, g_z4);
    cudaGetSymbolAddress((void**)&x_h, g_x_h);     cudaGetSymbolAddress((void**)&x_l, g_x_l);
    cudaGetSymbolAddress((void**)&aggx_h, g_aggx_h); cudaGetSymbolAddress((void**)&aggx_l, g_aggx_l);
    cudaGetSymbolAddress((void**)&h1_h, g_h1_h);   cudaGetSymbolAddress((void**)&h1_l, g_h1_l);
    cudaGetSymbolAddress((void**)&h2_h, g_h2_h);   cudaGetSymbolAddress((void**)&h2_l, g_h2_l);
    cudaGetSymbolAddress((void**)&ah2_h, g_ah2_h); cudaGetSymbolAddress((void**)&ah2_l, g_ah2_l);
    cudaGetSymbolAddress((void**)&h3_h, g_h3_h);   cudaGetSymbolAddress((void**)&h3_l, g_h3_l);
    cudaGetSymbolAddress((void**)&w1r_h, g_w1r_h); cudaGetSymbolAddress((void**)&w1r_l, g_w1r_l);
    cudaGetSymbolAddress((void**)&w1o_h, g_w1o_h); cudaGetSymbolAddress((void**)&w1o_l, g_w1o_l);
    cudaGetSymbolAddress((void**)&w2_h, g_w2_h);   cudaGetSymbolAddress((void**)&w2_l, g_w2_l);
    cudaGetSymbolAddress((void**)&w3r_h, g_w3r_h); cudaGetSymbolAddress((void**)&w3r_l, g_w3r_l);
    cudaGetSymbolAddress((void**)&w3o_h, g_w3o_h); cudaGetSymbolAddress((void**)&w3o_l, g_w3o_l);
    cudaGetSymbolAddress((void**)&w4_h, g_w4_h);   cudaGetSymbolAddress((void**)&w4_l, g_w4_l);

    const int T = 256;
    const int MB = (NNODES + 127) / 128;   // 391
    constexpr int SMEM = 2 * GSTAGE;       // 81920

    cudaFuncSetAttribute(mmagemm<true,  true,  true,  true >, cudaFuncAttributeMaxDynamicSharedMemorySize, SMEM);
    cudaFuncSetAttribute(mmagemm<false, false, false, false>, cudaFuncAttributeMaxDynamicSharedMemorySize, SMEM);

    // ---- index dtype detect + convert; zero scratch; split static operands
    detect_kernel<<<1, 1>>>(ei_raw);
    convert_kernel<<<(2 * NEDGES + T - 1) / T, T>>>(ei_raw, batch_raw);
    zero_all_kernel<<<1024, T>>>();
    split_static_kernel<<<1024, T>>>(W1_rel, W1_root, W2_rel, W2_root,
                                     W3_rel, W3_root, W4_rel, W4_root, x);

    // ---- L1: agg(x) then dual-A MMA -> h1 (bf16 hi/lo, relu, bias)
    edge_agg_kernel<64><<<(NEDGES * 16 + T - 1) / T, T>>>(x, D_IN, aggx, D_IN);
    split_kernel<<<1024, T>>>(aggx, aggx_h, aggx_l, NNODES * D_IN);
    {
        dim3 grid((D_H + 127) / 128, MB);
        mmagemm<true, true, true, true><<<grid, T, SMEM>>>(
            nullptr, h1_h, h1_l,
            aggx_h, aggx_l, x_h, x_l,
            w1r_h, w1r_l, w1o_h, w1o_l,
            b1, NNODES, D_IN, D_H);
    }

    // ---- L2: single-A MMA (K=1000, O=256 cat) -> z2 fp32
    {
        dim3 grid(2, MB);
        mmagemm<false, false, false, false><<<grid, T, SMEM>>>(
            z2, nullptr, nullptr,
            h1_h, h1_l, nullptr, nullptr,
            w2_h, w2_l, nullptr, nullptr,
            nullptr, NNODES, D_H, 256);
    }
    edge_agg_kernel<128><<<(NEDGES * 32 + T - 1) / T, T>>>(z2, 256, aggy, D_ENC);
    combine_pool_kernel<<<(NNODES * D_ENC + T - 1) / T, T>>>(b2);
    encoded_kernel<<<(NGRAPH * D_ENC + T - 1) / T, T>>>(enc);

    // ---- L3: agg(h2) then dual-A MMA -> h3 (bf16 hi/lo, relu, bias)
    edge_agg_kernel<128><<<(NEDGES * 32 + T - 1) / T, T>>>(h2f, D_ENC, aggh2, D_ENC);
    split_kernel<<<1024, T>>>(aggh2, ah2_h, ah2_l, NNODES * D_ENC);
    {
        dim3 grid((D_H + 127) / 128, MB);
        mmagemm<true, true, true, true><<<grid, T, SMEM>>>(
            nullptr, h3_h, h3_l,
            ah2_h, ah2_l, h2_h, h2_l,
            w3r_h, w3r_l, w3o_h, w3o_l,
            b3, NNODES, D_ENC, D_H);
    }

    // ---- L4: single-A MMA (K=1000, O=128 cat) -> z4 fp32
    {
        dim3 grid(1, MB);
        mmagemm<false, false, false, false><<<grid, T, SMEM>>>(
            z4, nullptr, nullptr,
            h3_h, h3_l, nullptr, nullptr,
            w4_h, w4_l, nullptr, nullptr,
            nullptr, NNODES, D_H, 128);
    }
    out_init_kernel<<<(NNODES * D_IN + T - 1) / T, T>>>(out, b4);
    edge_agg_kernel<64><<<(NEDGES * 16 + T - 1) / T, T>>>(z4, 128, out, D_IN);
}